// round 2
// baseline (speedup 1.0000x reference)
#include <cuda_runtime.h>
#include <math.h>

#define NPTS 16384
#define CDIM 64
#define ODIM 128
#define KNN  16
#define TI   128
#define TJ   128
#define TPAD 132   // 128 + 4, keeps 16B alignment of k-rows, conflict-light

// Scratch (device globals: no allocation allowed in kernel_launch)
__device__ float g_sq[NPTS];
__device__ float g_A[NPTS * ODIM];
__device__ float g_B[NPTS * ODIM];
__device__ int   g_idx[NPTS * KNN];

// Packed f32x2 helpers (Blackwell: ptxas never auto-fuses; PTX-only path)
__device__ __forceinline__ unsigned long long dup_f32x2(float a) {
    unsigned long long r;
    asm("mov.b64 %0, {%1, %1};" : "=l"(r) : "f"(a));
    return r;
}
__device__ __forceinline__ void fma_f32x2(unsigned long long& d,
                                          unsigned long long a,
                                          unsigned long long b) {
    asm("fma.rn.f32x2 %0, %1, %2, %0;" : "+l"(d) : "l"(a), "l"(b));
}
__device__ __forceinline__ void unpack_f32x2(float& lo, float& hi, unsigned long long v) {
    asm("mov.b64 {%0, %1}, %2;" : "=f"(lo), "=f"(hi) : "l"(v));
}

// ---------------------------------------------------------------------------
// Kernel 1: A = x@(W1a - W1b) + b1 ; B = x@W1b ; sq = ||x||^2
// ---------------------------------------------------------------------------
__global__ __launch_bounds__(128) void prep_kernel(
    const float* __restrict__ x,
    const float* __restrict__ W1,
    const float* __restrict__ b1)
{
    extern __shared__ float sm[];
    float* Wa = sm;                    // 64*128
    float* Wb = sm + CDIM * ODIM;      // 64*128
    float* xr = sm + 2 * CDIM * ODIM;  // 64

    const int tid = threadIdx.x;
    for (int e = tid; e < CDIM * ODIM; e += 128) {
        int c = e / ODIM, o = e % ODIM;
        float w1b = W1[(CDIM + c) * ODIM + o];
        Wa[e] = W1[c * ODIM + o] - w1b;
        Wb[e] = w1b;
    }
    float b1v = b1[tid];
    __syncthreads();

    const int NB = 16;
    const int base = blockIdx.x * NB;
    for (int r = 0; r < NB; r++) {
        int n = base + r;
        if (tid < CDIM) xr[tid] = x[n * CDIM + tid];
        __syncthreads();
        float a = b1v, b = 0.f;
#pragma unroll
        for (int c = 0; c < CDIM; c++) {
            float xc = xr[c];
            a = fmaf(xc, Wa[c * ODIM + tid], a);
            b = fmaf(xc, Wb[c * ODIM + tid], b);
        }
        g_A[n * ODIM + tid] = a;
        g_B[n * ODIM + tid] = b;
        if (tid < 32) {
            float p = xr[tid] * xr[tid] + xr[tid + 32] * xr[tid + 32];
#pragma unroll
            for (int off = 16; off; off >>= 1)
                p += __shfl_down_sync(0xffffffffu, p, off);
            if (tid == 0) g_sq[n] = p;
        }
        __syncthreads();
    }
}

// ---------------------------------------------------------------------------
// Kernel 2: fused distance GEMM (128x128x64 tiles, 8x8/thread, packed f32x2)
//           + per-row top-16 selection
// ---------------------------------------------------------------------------
__global__ __launch_bounds__(256, 1) void knn_kernel(const float* __restrict__ x)
{
    extern __shared__ float sm[];
    float* As   = sm;                    // 64 * TPAD (k-major, transposed)
    float* Bs   = As + CDIM * TPAD;      // 64 * TPAD
    float* Ds   = Bs + CDIM * TPAD;      // TI * TPAD (d2 tile)
    float* sqi  = Ds + TI * TPAD;        // TI
    float* bsq  = sqi + TI;              // TJ
    float* topd = bsq + TJ;              // TI * KNN
    float* wst  = topd + TI * KNN;       // TI
    int*   topi = (int*)(wst + TI);      // TI * KNN

    const int tid  = threadIdx.x;
    const int tx   = tid & 15;
    const int ty   = tid >> 4;
    const int lane = tid & 31;
    const int wid  = tid >> 5;
    const int ibase = blockIdx.x * TI;
    const unsigned FULL = 0xffffffffu;

    for (int e = tid; e < TI * KNN; e += 256) topd[e] = 3.4e38f;
    for (int e = tid; e < TI; e += 256) wst[e] = 3.4e38f;

    // Load Xi tile transposed (k-major) once
    for (int e = tid; e < TI * CDIM; e += 256) {
        int r = e >> 6, c = e & 63;
        As[c * TPAD + r] = x[(ibase + r) * CDIM + c];
    }
    if (tid < TI) sqi[tid] = g_sq[ibase + tid];
    __syncthreads();

    float sir[8];
#pragma unroll
    for (int m = 0; m < 8; m++) sir[m] = sqi[ty * 8 + m];

    for (int jbase = 0; jbase < NPTS; jbase += TJ) {
        // Load Xj tile transposed + its norms
        for (int e = tid; e < TJ * CDIM; e += 256) {
            int r = e >> 6, c = e & 63;
            Bs[c * TPAD + r] = x[(jbase + r) * CDIM + c];
        }
        if (tid < TJ) bsq[tid] = g_sq[jbase + tid];
        __syncthreads();

        // 128x128x64 GEMM, 8x8 per thread, n-pairs packed into f32x2.
        // Each packed lane runs the same fma chain as the scalar version ->
        // bitwise-identical results.
        unsigned long long acc2[8][4];
#pragma unroll
        for (int m = 0; m < 8; m++)
#pragma unroll
            for (int n = 0; n < 4; n++) acc2[m][n] = 0ull;

#pragma unroll 4
        for (int k = 0; k < CDIM; k++) {
            const float4 a0 = *(const float4*)(As + k * TPAD + ty * 8);
            const float4 a1 = *(const float4*)(As + k * TPAD + ty * 8 + 4);
            const unsigned long long* bp =
                (const unsigned long long*)(Bs + k * TPAD + tx * 8);
            unsigned long long bv[4] = {bp[0], bp[1], bp[2], bp[3]};
            unsigned long long ap[8];
            ap[0] = dup_f32x2(a0.x); ap[1] = dup_f32x2(a0.y);
            ap[2] = dup_f32x2(a0.z); ap[3] = dup_f32x2(a0.w);
            ap[4] = dup_f32x2(a1.x); ap[5] = dup_f32x2(a1.y);
            ap[6] = dup_f32x2(a1.z); ap[7] = dup_f32x2(a1.w);
#pragma unroll
            for (int m = 0; m < 8; m++)
#pragma unroll
                for (int n = 0; n < 4; n++)
                    fma_f32x2(acc2[m][n], ap[m], bv[n]);
        }

        // d2 = sq_i + sq_j - 2*dot -> Ds
        float bq[8];
        *(float4*)&bq[0] = *(const float4*)(bsq + tx * 8);
        *(float4*)&bq[4] = *(const float4*)(bsq + tx * 8 + 4);
#pragma unroll
        for (int m = 0; m < 8; m++) {
            float a[8];
            unpack_f32x2(a[0], a[1], acc2[m][0]);
            unpack_f32x2(a[2], a[3], acc2[m][1]);
            unpack_f32x2(a[4], a[5], acc2[m][2]);
            unpack_f32x2(a[6], a[7], acc2[m][3]);
            float* drow = Ds + (ty * 8 + m) * TPAD + tx * 8;
            float4 v0, v1;
            v0.x = sir[m] + bq[0] - 2.f * a[0];
            v0.y = sir[m] + bq[1] - 2.f * a[1];
            v0.z = sir[m] + bq[2] - 2.f * a[2];
            v0.w = sir[m] + bq[3] - 2.f * a[3];
            v1.x = sir[m] + bq[4] - 2.f * a[4];
            v1.y = sir[m] + bq[5] - 2.f * a[5];
            v1.z = sir[m] + bq[6] - 2.f * a[6];
            v1.w = sir[m] + bq[7] - 2.f * a[7];
            *(float4*)drow       = v0;
            *(float4*)(drow + 4) = v1;
        }
        __syncthreads();

        // Per-row top-16 update: warp w owns rows [w*16, w*16+16)
        for (int rr = 0; rr < 16; rr++) {
            const int r = wid * 16 + rr;
            float w = wst[r];
#pragma unroll
            for (int jj = 0; jj < 4; jj++) {
                float v = Ds[r * TPAD + jj * 32 + lane];
                unsigned ball = __ballot_sync(FULL, v < w);
                while (ball) {
                    int src = __ffs(ball) - 1;
                    ball &= ball - 1;
                    float vv = __shfl_sync(FULL, v, src);
                    if (!(vv < w)) continue;   // threshold may have tightened
                    int jidx = jbase + jj * 32 + src;
                    // warp argmax over the 16 kept slots
                    float tv = (lane < KNN) ? topd[r * KNN + lane] : -3.4e38f;
                    int tp = lane;
#pragma unroll
                    for (int off = 8; off >= 1; off >>= 1) {
                        float ov = __shfl_down_sync(FULL, tv, off);
                        int   op = __shfl_down_sync(FULL, tp, off);
                        if (ov > tv) { tv = ov; tp = op; }
                    }
                    float mx = __shfl_sync(FULL, tv, 0);
                    int   mp = __shfl_sync(FULL, tp, 0);
                    if (vv < mx) {
                        if (lane == mp) {
                            topd[r * KNN + mp] = vv;
                            topi[r * KNN + mp] = jidx;
                        }
                        __syncwarp(FULL);
                        float t2 = (lane < KNN) ? topd[r * KNN + lane] : -3.4e38f;
#pragma unroll
                        for (int off = 8; off >= 1; off >>= 1) {
                            float o2 = __shfl_down_sync(FULL, t2, off);
                            if (o2 > t2) t2 = o2;
                        }
                        w = __shfl_sync(FULL, t2, 0);
                    }
                }
            }
            if (lane == 0) wst[r] = w;
        }
        __syncthreads();
    }

    for (int e = tid; e < TI * KNN; e += 256)
        g_idx[(ibase + (e >> 4)) * KNN + (e & 15)] = topi[e];
}

// ---------------------------------------------------------------------------
// Kernel 3: s[n] = mean_k relu(A[n] + B[idx[n,k]]) ; out = s @ W2 + b2
// ---------------------------------------------------------------------------
__global__ __launch_bounds__(128) void out_kernel(
    const float* __restrict__ W2,
    const float* __restrict__ b2,
    float* __restrict__ out)
{
    extern __shared__ float sm[];
    float* W2s = sm;                 // 128*128
    float* s_s = sm + ODIM * ODIM;   // 128
    int*   nbr = (int*)(s_s + ODIM); // 16

    const int tid = threadIdx.x;
    for (int e = tid; e < ODIM * ODIM; e += 128) W2s[e] = W2[e];
    float b2v = b2[tid];
    __syncthreads();

    for (int n = blockIdx.x; n < NPTS; n += gridDim.x) {
        if (tid < KNN) nbr[tid] = g_idx[n * KNN + tid];
        __syncthreads();
        float a = g_A[n * ODIM + tid];
        float acc = 0.f;
#pragma unroll
        for (int k = 0; k < KNN; k++)
            acc += fmaxf(a + g_B[nbr[k] * ODIM + tid], 0.f);
        s_s[tid] = acc * (1.0f / KNN);
        __syncthreads();
        float o = b2v;
#pragma unroll 8
        for (int p = 0; p < ODIM; p++)
            o = fmaf(s_s[p], W2s[p * ODIM + tid], o);
        out[n * ODIM + tid] = o;
        __syncthreads();
    }
}

// ---------------------------------------------------------------------------
extern "C" void kernel_launch(void* const* d_in, const int* in_sizes, int n_in,
                              void* d_out, int out_size)
{
    const float* x  = (const float*)d_in[0];
    const float* W1 = (const float*)d_in[1];
    const float* b1 = (const float*)d_in[2];
    const float* W2 = (const float*)d_in[3];
    const float* b2 = (const float*)d_in[4];
    float* out = (float*)d_out;

    const int sh1 = (2 * CDIM * ODIM + CDIM) * sizeof(float);               // ~65.8 KB
    const int sh2 = (2 * CDIM * TPAD + TI * TPAD + TI + TJ                   // tiles + norms
                     + TI * KNN + TI + TI * KNN) * sizeof(float);            // ~153 KB
    const int sh3 = (ODIM * ODIM + ODIM) * sizeof(float) + KNN * sizeof(int); // ~66 KB

    cudaFuncSetAttribute(prep_kernel, cudaFuncAttributeMaxDynamicSharedMemorySize, sh1);
    cudaFuncSetAttribute(knn_kernel,  cudaFuncAttributeMaxDynamicSharedMemorySize, sh2);
    cudaFuncSetAttribute(out_kernel,  cudaFuncAttributeMaxDynamicSharedMemorySize, sh3);

    prep_kernel<<<NPTS / 16, 128, sh1>>>(x, W1, b1);
    knn_kernel<<<NPTS / TI, 256, sh2>>>(x);
    out_kernel<<<1024, 128, sh3>>>(W2, b2, out);
}

// round 3
// speedup vs baseline: 1.0427x; 1.0427x over previous
#include <cuda_runtime.h>
#include <math.h>

#define NPTS 16384
#define CDIM 64
#define ODIM 128
#define KNN  16
#define TI   128
#define TJ   128
#define TPAD 130   // even: float2-aligned k-rows; 130 mod 32 = 2 -> conflict-light

// Scratch (device globals: no allocation allowed in kernel_launch)
__device__ float g_sq[NPTS];
__device__ float g_A[NPTS * ODIM];
__device__ float g_B[NPTS * ODIM];
__device__ int   g_idx[NPTS * KNN];

// Packed f32x2 helpers (ptxas never auto-fuses; PTX-only path)
__device__ __forceinline__ unsigned long long dup_f32x2(float a) {
    unsigned long long r;
    asm("mov.b64 %0, {%1, %1};" : "=l"(r) : "f"(a));
    return r;
}
__device__ __forceinline__ void fma_f32x2(unsigned long long& d,
                                          unsigned long long a,
                                          unsigned long long b) {
    asm("fma.rn.f32x2 %0, %1, %2, %0;" : "+l"(d) : "l"(a), "l"(b));
}
__device__ __forceinline__ void unpack_f32x2(float& lo, float& hi, unsigned long long v) {
    asm("mov.b64 {%0, %1}, %2;" : "=f"(lo), "=f"(hi) : "l"(v));
}

// ---------------------------------------------------------------------------
// Kernel 1: A = x@(W1a - W1b) + b1 ; B = x@W1b ; sq = ||x||^2
// ---------------------------------------------------------------------------
__global__ __launch_bounds__(128) void prep_kernel(
    const float* __restrict__ x,
    const float* __restrict__ W1,
    const float* __restrict__ b1)
{
    extern __shared__ float sm[];
    float* Wa = sm;                    // 64*128
    float* Wb = sm + CDIM * ODIM;      // 64*128
    float* xr = sm + 2 * CDIM * ODIM;  // 2*64 double buffer

    const int tid = threadIdx.x;
    for (int e = tid; e < CDIM * ODIM; e += 128) {
        int c = e / ODIM, o = e % ODIM;
        float w1b = W1[(CDIM + c) * ODIM + o];
        Wa[e] = W1[c * ODIM + o] - w1b;
        Wb[e] = w1b;
    }
    float b1v = b1[tid];

    const int NB = 16;
    const int base = blockIdx.x * NB;
    if (tid < CDIM) xr[tid] = x[base * CDIM + tid];
    __syncthreads();

    for (int r = 0; r < NB; r++) {
        const int n = base + r;
        const float* xb = xr + (r & 1) * CDIM;
        // 4 independent FMA chains (2 per output) for ILP
        float a0 = b1v, a1 = 0.f, b0 = 0.f, b1a = 0.f;
#pragma unroll
        for (int c = 0; c < CDIM; c += 2) {
            float x0 = xb[c], x1 = xb[c + 1];
            a0  = fmaf(x0, Wa[c * ODIM + tid], a0);
            a1  = fmaf(x1, Wa[(c + 1) * ODIM + tid], a1);
            b0  = fmaf(x0, Wb[c * ODIM + tid], b0);
            b1a = fmaf(x1, Wb[(c + 1) * ODIM + tid], b1a);
        }
        g_A[n * ODIM + tid] = a0 + a1;
        g_B[n * ODIM + tid] = b0 + b1a;
        if (tid < 32) {
            float p = xb[tid] * xb[tid] + xb[tid + 32] * xb[tid + 32];
#pragma unroll
            for (int off = 16; off; off >>= 1)
                p += __shfl_down_sync(0xffffffffu, p, off);
            if (tid == 0) g_sq[n] = p;
        }
        // prefetch next row into the other buffer
        if (r + 1 < NB) {
            __syncthreads();
            if (tid < CDIM) xr[((r + 1) & 1) * CDIM + tid] = x[(n + 1) * CDIM + tid];
            __syncthreads();
        }
    }
}

// ---------------------------------------------------------------------------
// Kernel 2: fused distance GEMM (128x128x64 tiles, 8x8/thread, packed f32x2,
//           conflict-free smem layout) + per-row top-16 selection
// Column mapping per thread: pairs {2tx, 2tx+1} + 32n, n=0..3
// ---------------------------------------------------------------------------
__global__ __launch_bounds__(256, 1) void knn_kernel(const float* __restrict__ x)
{
    extern __shared__ float sm[];
    float* As   = sm;                    // 64 * TPAD (k-major, transposed)
    float* Bs   = As + CDIM * TPAD;      // 64 * TPAD
    float* Ds   = Bs + CDIM * TPAD;      // TI * TPAD (d2 tile)
    float* sqi  = Ds + TI * TPAD;        // TI
    float* bsq  = sqi + TI;              // TJ
    float* topd = bsq + TJ;              // TI * KNN
    float* wst  = topd + TI * KNN;       // TI
    int*   topi = (int*)(wst + TI);      // TI * KNN

    const int tid  = threadIdx.x;
    const int tx   = tid & 15;
    const int ty   = tid >> 4;
    const int lane = tid & 31;
    const int wid  = tid >> 5;
    const int ibase = blockIdx.x * TI;
    const unsigned FULL = 0xffffffffu;

    for (int e = tid; e < TI * KNN; e += 256) topd[e] = 3.4e38f;
    for (int e = tid; e < TI; e += 256) wst[e] = 3.4e38f;

    // Load Xi tile transposed, float4 global loads (coalesced)
    for (int e = tid; e < TI * CDIM / 4; e += 256) {
        int r = e >> 4, c4 = e & 15;
        float4 v = *(const float4*)(x + (ibase + r) * CDIM + c4 * 4);
        As[(c4 * 4 + 0) * TPAD + r] = v.x;
        As[(c4 * 4 + 1) * TPAD + r] = v.y;
        As[(c4 * 4 + 2) * TPAD + r] = v.z;
        As[(c4 * 4 + 3) * TPAD + r] = v.w;
    }
    if (tid < TI) sqi[tid] = g_sq[ibase + tid];
    __syncthreads();

    float sir[8];
#pragma unroll
    for (int m = 0; m < 8; m++) sir[m] = sqi[ty * 8 + m];

    for (int jbase = 0; jbase < NPTS; jbase += TJ) {
        for (int e = tid; e < TJ * CDIM / 4; e += 256) {
            int r = e >> 4, c4 = e & 15;
            float4 v = *(const float4*)(x + (jbase + r) * CDIM + c4 * 4);
            Bs[(c4 * 4 + 0) * TPAD + r] = v.x;
            Bs[(c4 * 4 + 1) * TPAD + r] = v.y;
            Bs[(c4 * 4 + 2) * TPAD + r] = v.z;
            Bs[(c4 * 4 + 3) * TPAD + r] = v.w;
        }
        if (tid < TJ) bsq[tid] = g_sq[jbase + tid];
        __syncthreads();

        // GEMM: acc2[m][n] packs columns (32n+2tx, 32n+2tx+1) for row ty*8+m.
        // Per-element FMA chain identical to scalar version -> bitwise-same d2.
        unsigned long long acc2[8][4];
#pragma unroll
        for (int m = 0; m < 8; m++)
#pragma unroll
            for (int n = 0; n < 4; n++) acc2[m][n] = 0ull;

#pragma unroll 4
        for (int k = 0; k < CDIM; k++) {
            const unsigned long long* arow =
                (const unsigned long long*)(As + k * TPAD + ty * 8);
            const float* brow = Bs + k * TPAD + tx * 2;
            unsigned long long bv[4];
            bv[0] = *(const unsigned long long*)(brow);
            bv[1] = *(const unsigned long long*)(brow + 32);
            bv[2] = *(const unsigned long long*)(brow + 64);
            bv[3] = *(const unsigned long long*)(brow + 96);
            unsigned long long ap[8];
#pragma unroll
            for (int u = 0; u < 4; u++) {
                float lo, hi;
                unpack_f32x2(lo, hi, arow[u]);
                ap[2 * u]     = dup_f32x2(lo);
                ap[2 * u + 1] = dup_f32x2(hi);
            }
#pragma unroll
            for (int m = 0; m < 8; m++)
#pragma unroll
                for (int n = 0; n < 4; n++)
                    fma_f32x2(acc2[m][n], ap[m], bv[n]);
        }

        // d2 = sq_i + sq_j - 2*dot -> Ds (float2 stores, conflict-free)
        float bq[8];
        {
            const float* bb = bsq + tx * 2;
#pragma unroll
            for (int n = 0; n < 4; n++) {
                bq[2 * n]     = bb[32 * n];
                bq[2 * n + 1] = bb[32 * n + 1];
            }
        }
#pragma unroll
        for (int m = 0; m < 8; m++) {
            float* drow = Ds + (ty * 8 + m) * TPAD + tx * 2;
#pragma unroll
            for (int n = 0; n < 4; n++) {
                float lo, hi;
                unpack_f32x2(lo, hi, acc2[m][n]);
                float2 v;
                v.x = sir[m] + bq[2 * n]     - 2.f * lo;
                v.y = sir[m] + bq[2 * n + 1] - 2.f * hi;
                *(float2*)(drow + 32 * n) = v;
            }
        }
        __syncthreads();

        // Per-row top-16 update: warp w owns rows [w*16, w*16+16)
        for (int rr = 0; rr < 16; rr++) {
            const int r = wid * 16 + rr;
            float w = wst[r];
#pragma unroll
            for (int jj = 0; jj < 4; jj++) {
                float v = Ds[r * TPAD + jj * 32 + lane];
                unsigned ball = __ballot_sync(FULL, v < w);
                while (ball) {
                    int src = __ffs(ball) - 1;
                    ball &= ball - 1;
                    float vv = __shfl_sync(FULL, v, src);
                    if (!(vv < w)) continue;   // threshold may have tightened
                    int jidx = jbase + jj * 32 + src;
                    // warp argmax over the 16 kept slots
                    float tv = (lane < KNN) ? topd[r * KNN + lane] : -3.4e38f;
                    int tp = lane;
#pragma unroll
                    for (int off = 8; off >= 1; off >>= 1) {
                        float ov = __shfl_down_sync(FULL, tv, off);
                        int   op = __shfl_down_sync(FULL, tp, off);
                        if (ov > tv) { tv = ov; tp = op; }
                    }
                    float mx = __shfl_sync(FULL, tv, 0);
                    int   mp = __shfl_sync(FULL, tp, 0);
                    if (vv < mx) {
                        if (lane == mp) {
                            topd[r * KNN + mp] = vv;
                            topi[r * KNN + mp] = jidx;
                        }
                        __syncwarp(FULL);
                        float t2 = (lane < KNN) ? topd[r * KNN + lane] : -3.4e38f;
#pragma unroll
                        for (int off = 8; off >= 1; off >>= 1) {
                            float o2 = __shfl_down_sync(FULL, t2, off);
                            if (o2 > t2) t2 = o2;
                        }
                        w = __shfl_sync(FULL, t2, 0);
                    }
                }
            }
            if (lane == 0) wst[r] = w;
        }
        __syncthreads();
    }

    for (int e = tid; e < TI * KNN; e += 256)
        g_idx[(ibase + (e >> 4)) * KNN + (e & 15)] = topi[e];
}

// ---------------------------------------------------------------------------
// Kernel 3: s[n] = mean_k relu(A[n] + B[idx[n,k]]) ; out = s @ W2 + b2
// ---------------------------------------------------------------------------
__global__ __launch_bounds__(128) void out_kernel(
    const float* __restrict__ W2,
    const float* __restrict__ b2,
    float* __restrict__ out)
{
    extern __shared__ float sm[];
    float* W2s = sm;                 // 128*128
    float* s_s = sm + ODIM * ODIM;   // 128
    int*   nbr = (int*)(s_s + ODIM); // 16

    const int tid = threadIdx.x;
    for (int e = tid; e < ODIM * ODIM; e += 128) W2s[e] = W2[e];
    float b2v = b2[tid];
    __syncthreads();

    for (int n = blockIdx.x; n < NPTS; n += gridDim.x) {
        if (tid < KNN) nbr[tid] = g_idx[n * KNN + tid];
        __syncthreads();
        float a = g_A[n * ODIM + tid];
        float acc = 0.f;
#pragma unroll
        for (int k = 0; k < KNN; k++)
            acc += fmaxf(a + g_B[nbr[k] * ODIM + tid], 0.f);
        s_s[tid] = acc * (1.0f / KNN);
        __syncthreads();
        // two independent chains for ILP
        float o0 = b2v, o1 = 0.f;
#pragma unroll 8
        for (int p = 0; p < ODIM; p += 2) {
            o0 = fmaf(s_s[p],     W2s[p * ODIM + tid],       o0);
            o1 = fmaf(s_s[p + 1], W2s[(p + 1) * ODIM + tid], o1);
        }
        out[n * ODIM + tid] = o0 + o1;
        __syncthreads();
    }
}

// ---------------------------------------------------------------------------
extern "C" void kernel_launch(void* const* d_in, const int* in_sizes, int n_in,
                              void* d_out, int out_size)
{
    const float* x  = (const float*)d_in[0];
    const float* W1 = (const float*)d_in[1];
    const float* b1 = (const float*)d_in[2];
    const float* W2 = (const float*)d_in[3];
    const float* b2 = (const float*)d_in[4];
    float* out = (float*)d_out;

    const int sh1 = (2 * CDIM * ODIM + 2 * CDIM) * sizeof(float);
    const int sh2 = (2 * CDIM * TPAD + TI * TPAD + TI + TJ
                     + TI * KNN + TI + TI * KNN) * sizeof(float);
    const int sh3 = (ODIM * ODIM + ODIM) * sizeof(float) + KNN * sizeof(int);

    cudaFuncSetAttribute(prep_kernel, cudaFuncAttributeMaxDynamicSharedMemorySize, sh1);
    cudaFuncSetAttribute(knn_kernel,  cudaFuncAttributeMaxDynamicSharedMemorySize, sh2);
    cudaFuncSetAttribute(out_kernel,  cudaFuncAttributeMaxDynamicSharedMemorySize, sh3);

    prep_kernel<<<NPTS / 16, 128, sh1>>>(x, W1, b1);
    knn_kernel<<<NPTS / TI, 256, sh2>>>(x);
    out_kernel<<<1024, 128, sh3>>>(W2, b2, out);
}